// round 3
// baseline (speedup 1.0000x reference)
#include <cuda_runtime.h>

// Problem constants (fixed by dataset): B=1, N=4096, C=8, H=W=128, K=8
#define MAXN 8192
constexpr float RADIUS = 0.05f;
constexpr int H = 128, W = 128, C = 8, K = 8;
constexpr int TILE = 8;             // 8x8 pixel tiles
constexpr int TX = W / TILE;        // 16
constexpr int TY = H / TILE;        // 16
constexpr int NTILES = TX * TY;     // 256
constexpr int TPB = TILE * TILE;    // 64 threads (one per pixel)
constexpr int NBLK = NTILES;        // 256 blocks, one per tile
constexpr int CAP = 4096;           // per-tile bin capacity (cannot overflow: N<=4096)
constexpr int SCHUNK = 256;         // candidates staged through smem per pass

// Scratch (no cudaMalloc allowed -> __device__ globals).
// g_cnt is zeroed statically at load and re-zeroed by the render phase each
// invocation, so every call (and every graph replay) starts clean.
__device__ int    g_cnt[NTILES];
__device__ float4 g_bins[NTILES * CAP];   // (px, py, z, idx-as-float)

// Self-resetting sense/epoch global barrier. g_count wraps to 0 via atomicInc;
// g_epoch is monotonic across invocations — safe under graph replay.
__device__ unsigned int          g_count = 0;
__device__ volatile unsigned int g_epoch = 0;

__device__ __forceinline__ void global_barrier() {
    __syncthreads();
    if (threadIdx.x == 0) {
        __threadfence();                       // publish this block's bin writes
        unsigned int e = g_epoch;
        if (atomicInc(&g_count, NBLK - 1) == NBLK - 1) {
            g_epoch = e + 1;                   // release all waiters
        } else {
            while (g_epoch == e) { }
        }
    }
    __syncthreads();
}

__global__ void __launch_bounds__(TPB, 8)
fused_render_kernel(const float* __restrict__ pts,
                    const float* __restrict__ feat,
                    float* __restrict__ out, int n) {
    __shared__ float4 sc[SCHUNK];

    const int tile = blockIdx.x;
    const int tx = tile & (TX - 1);
    const int ty = tile >> 4;

    // ---------------- Phase 1: project + bin (one point per thread) ----------
    {
        int i = blockIdx.x * TPB + threadIdx.x;   // 0..16383 covers N=4096
        if (i < n) {
            float x = pts[3 * i + 0];
            float y = pts[3 * i + 1];
            float z = pts[3 * i + 2];
            if (z > 0.0f) {
                float px = x / z;
                float py = y / z;
                // continuous pixel coordinate (pixel ix center at u = ix)
                float u = (px + 1.0f) * (0.5f * (float)W) - 0.5f;
                float v = (py + 1.0f) * (0.5f * (float)H) - 0.5f;
                const float PR = 3.25f;           // 3.2 px splat reach + eps
                int bx0 = max(0,      (int)floorf((u - PR) * (1.0f / TILE)));
                int bx1 = min(TX - 1, (int)floorf((u + PR) * (1.0f / TILE)));
                int by0 = max(0,      (int)floorf((v - PR) * (1.0f / TILE)));
                int by1 = min(TY - 1, (int)floorf((v + PR) * (1.0f / TILE)));
                if (bx0 <= bx1 && by0 <= by1) {
                    float4 rec = make_float4(px, py, z, __int_as_float(i));
                    for (int by = by0; by <= by1; by++)
                        for (int bx = bx0; bx <= bx1; bx++) {
                            int t = by * TX + bx;
                            int slot = atomicAdd(&g_cnt[t], 1);
                            g_bins[t * CAP + slot] = rec;
                        }
                }
            }
        }
    }

    global_barrier();

    // ---------------- Phase 2: render this block's tile ----------------------
    const int lx = threadIdx.x & (TILE - 1);
    const int ly = threadIdx.x >> 3;
    const int ix = tx * TILE + lx;
    const int iy = ty * TILE + ly;

    const float gx = ((float)ix + 0.5f) * (2.0f / (float)W) - 1.0f;
    const float gy = ((float)iy + 0.5f) * (2.0f / (float)H) - 1.0f;
    const float r2 = RADIUS * RADIUS;

    float bz[K], bd[K];
    int   bi[K];
    #pragma unroll
    for (int k = 0; k < K; k++) { bz[k] = 3.0e38f; bd[k] = 0.0f; bi[k] = 0; }

    const int cnt = atomicAdd(&g_cnt[tile], 0);   // L2 read (coherent)
    if (threadIdx.x == 0) g_cnt[tile] = 0;        // leave clean for next replay
    const float4* __restrict__ bins = &g_bins[tile * CAP];

    for (int base = 0; base < cnt; base += SCHUNK) {
        const int m = min(SCHUNK, cnt - base);
        for (int j = threadIdx.x; j < m; j += TPB)
            sc[j] = bins[base + j];
        __syncthreads();

        for (int j = 0; j < m; j++) {
            float4 c = sc[j];
            float dx = gx - c.x;
            float dy = gy - c.y;
            float d2 = dx * dx + dy * dy;
            // strict '<' on z: distinct depths -> order-independent top-K set
            if (d2 < r2 && c.z < bz[K - 1]) {
                bz[K - 1] = c.z; bd[K - 1] = d2; bi[K - 1] = __float_as_int(c.w);
                #pragma unroll
                for (int k = K - 1; k > 0; k--) {
                    if (bz[k] < bz[k - 1]) {
                        float t0 = bz[k]; bz[k] = bz[k - 1]; bz[k - 1] = t0;
                        float t1 = bd[k]; bd[k] = bd[k - 1]; bd[k - 1] = t1;
                        int   t2 = bi[k]; bi[k] = bi[k - 1]; bi[k - 1] = t2;
                    }
                }
            }
        }
        __syncthreads();
    }

    // front-to-back alpha compositing
    float acc[C];
    #pragma unroll
    for (int c = 0; c < C; c++) acc[c] = 0.0f;
    float T = 1.0f;
    const float inv_r2 = 1.0f / r2;

    #pragma unroll
    for (int k = 0; k < K; k++) {
        if (bz[k] < 1.0e38f) {
            float a = 1.0f - bd[k] * inv_r2;
            a = fminf(fmaxf(a, 0.0f), 1.0f);
            float w = a * T;
            const float4* f = (const float4*)(feat + (size_t)bi[k] * C);
            float4 f0 = __ldg(&f[0]);
            float4 f1 = __ldg(&f[1]);
            acc[0] += w * f0.x; acc[1] += w * f0.y;
            acc[2] += w * f0.z; acc[3] += w * f0.w;
            acc[4] += w * f1.x; acc[5] += w * f1.y;
            acc[6] += w * f1.z; acc[7] += w * f1.w;
            T *= (1.0f - a);
        }
    }

    float4* o = (float4*)(out + (size_t)(iy * W + ix) * C);
    o[0] = make_float4(acc[0], acc[1], acc[2], acc[3]);
    o[1] = make_float4(acc[4], acc[5], acc[6], acc[7]);
}

extern "C" void kernel_launch(void* const* d_in, const int* in_sizes, int n_in,
                              void* d_out, int out_size) {
    const float* pts  = (const float*)d_in[0];   // [B,N,3] f32
    const float* feat = (const float*)d_in[1];   // [B,N,C] f32
    float* out = (float*)d_out;                  // [B,H,W,C] f32
    int n = in_sizes[0] / 3;                     // B=1 -> N
    if (n > MAXN) n = MAXN;

    fused_render_kernel<<<NBLK, TPB>>>(pts, feat, out, n);
}

// round 4
// speedup vs baseline: 1.2063x; 1.2063x over previous
#include <cuda_runtime.h>

// Problem constants (fixed by dataset): B=1, N=4096, C=8, H=W=128, K=8
#define MAXN 8192
constexpr float RADIUS = 0.05f;
constexpr int H = 128, W = 128, C = 8, K = 8;
constexpr int TILE = 8;             // 8x8 pixel tiles
constexpr int TX = W / TILE;        // 16
constexpr int TY = H / TILE;        // 16
constexpr int NTILES = TX * TY;     // 256 blocks, one per tile
constexpr int PIX = TILE * TILE;    // 64 pixels per tile
constexpr int SPLIT = 4;            // threads per pixel in scan phase
constexpr int TPB = PIX * SPLIT;    // 256 threads per block
constexpr int CAPT = 1280;          // smem candidate cap (expected ~52, huge margin)

// smem budget: candidates 1280*16 = 20480 B, merge lists 64*4*8*(4+4+4) = 24576 B
// total 45056 B + counters < 48 KB static limit.
constexpr int LISTN = PIX * SPLIT * K;   // 2048 merge-list entries

__global__ void __launch_bounds__(TPB)
render_kernel(const float* __restrict__ pts,
              const float* __restrict__ feat,
              float* __restrict__ out, int n) {
    __shared__ __align__(16) unsigned char raw[CAPT * 16 + LISTN * 12];
    float4* s_cand = (float4*)raw;
    float*  s_mz   = (float*)(raw + CAPT * 16);
    float*  s_md   = (float*)(raw + CAPT * 16 + LISTN * 4);
    int*    s_mi   = (int*)  (raw + CAPT * 16 + LISTN * 8);
    __shared__ int s_cnt;

    const int tile = blockIdx.x;
    const int tx = tile & (TX - 1);
    const int ty = tile >> 4;

    if (threadIdx.x == 0) s_cnt = 0;
    __syncthreads();

    // tile bounds over pixel centers, expanded by splat radius (conservative bbox cull;
    // exact d2 < r2 test happens in the scan phase)
    const float x0 = ((float)(tx * TILE)            + 0.5f) * (2.0f / W) - 1.0f - RADIUS;
    const float x1 = ((float)(tx * TILE + TILE - 1) + 0.5f) * (2.0f / W) - 1.0f + RADIUS;
    const float y0 = ((float)(ty * TILE)            + 0.5f) * (2.0f / H) - 1.0f - RADIUS;
    const float y1 = ((float)(ty * TILE + TILE - 1) + 0.5f) * (2.0f / H) - 1.0f + RADIUS;

    // -------- Phase 1: cull all points into smem candidate list (16 iters/thread)
    for (int i = threadIdx.x; i < n; i += TPB) {
        float x = pts[3 * i + 0];
        float y = pts[3 * i + 1];
        float z = pts[3 * i + 2];
        if (z > 0.0f) {
            float px = x / z;
            float py = y / z;
            if (px >= x0 && px <= x1 && py >= y0 && py <= y1) {
                int slot = atomicAdd(&s_cnt, 1);
                if (slot < CAPT)
                    s_cand[slot] = make_float4(px, py, z, __int_as_float(i));
            }
        }
    }
    __syncthreads();
    const int cnt = min(s_cnt, CAPT);

    // -------- Phase 2: split scan, 4 threads per pixel
    const int p = threadIdx.x >> 2;        // pixel 0..63
    const int s = threadIdx.x & 3;         // sub-lane 0..3
    const int lx = p & (TILE - 1);
    const int ly = p >> 3;
    const int ix = tx * TILE + lx;
    const int iy = ty * TILE + ly;

    const float gx = ((float)ix + 0.5f) * (2.0f / W) - 1.0f;
    const float gy = ((float)iy + 0.5f) * (2.0f / H) - 1.0f;
    const float r2 = RADIUS * RADIUS;

    float lz[K], ld[K];
    int   li[K];
    #pragma unroll
    for (int k = 0; k < K; k++) { lz[k] = 3.0e38f; ld[k] = 0.0f; li[k] = 0; }

    for (int j = s; j < cnt; j += SPLIT) {
        float4 c = s_cand[j];
        float dx = gx - c.x;
        float dy = gy - c.y;
        float d2 = dx * dx + dy * dy;
        // distinct depths -> top-K set is order-independent (matches top_k)
        if (d2 < r2 && c.z < lz[K - 1]) {
            lz[K - 1] = c.z; ld[K - 1] = d2; li[K - 1] = __float_as_int(c.w);
            #pragma unroll
            for (int k = K - 1; k > 0; k--) {
                if (lz[k] < lz[k - 1]) {
                    float t0 = lz[k]; lz[k] = lz[k - 1]; lz[k - 1] = t0;
                    float t1 = ld[k]; ld[k] = ld[k - 1]; ld[k - 1] = t1;
                    int   t2 = li[k]; li[k] = li[k - 1]; li[k - 1] = t2;
                }
            }
        }
    }

    // publish local sorted top-8 lists
    {
        int off = (p * SPLIT + s) * K;
        #pragma unroll
        for (int k = 0; k < K; k++) {
            s_mz[off + k] = lz[k];
            s_md[off + k] = ld[k];
            s_mi[off + k] = li[k];
        }
    }
    __syncthreads();

    // -------- Phase 3: 4-way merge + composite + store (one thread per pixel)
    if (s == 0) {
        int   hp[SPLIT];
        float hz[SPLIT];
        #pragma unroll
        for (int q = 0; q < SPLIT; q++) {
            hp[q] = (p * SPLIT + q) * K;
            hz[q] = s_mz[hp[q]];
        }

        float acc[C];
        #pragma unroll
        for (int c = 0; c < C; c++) acc[c] = 0.0f;
        float T = 1.0f;
        const float inv_r2 = 1.0f / r2;

        #pragma unroll
        for (int k = 0; k < K; k++) {
            int b = 0;
            if (hz[1] < hz[b]) b = 1;
            if (hz[2] < hz[b]) b = 2;
            if (hz[3] < hz[b]) b = 3;
            float zk = hz[b];
            if (zk < 1.0e38f) {
                float d2 = s_md[hp[b]];
                int   id = s_mi[hp[b]];
                float a = 1.0f - d2 * inv_r2;
                a = fminf(fmaxf(a, 0.0f), 1.0f);
                float w = a * T;
                const float4* f = (const float4*)(feat + (size_t)id * C);
                float4 f0 = __ldg(&f[0]);
                float4 f1 = __ldg(&f[1]);
                acc[0] += w * f0.x; acc[1] += w * f0.y;
                acc[2] += w * f0.z; acc[3] += w * f0.w;
                acc[4] += w * f1.x; acc[5] += w * f1.y;
                acc[6] += w * f1.z; acc[7] += w * f1.w;
                T *= (1.0f - a);
            }
            hp[b]++;
            hz[b] = ((hp[b] & (K - 1)) != 0) ? s_mz[hp[b]] : 3.0e38f;
        }

        float4* o = (float4*)(out + (size_t)(iy * W + ix) * C);
        o[0] = make_float4(acc[0], acc[1], acc[2], acc[3]);
        o[1] = make_float4(acc[4], acc[5], acc[6], acc[7]);
    }
}

extern "C" void kernel_launch(void* const* d_in, const int* in_sizes, int n_in,
                              void* d_out, int out_size) {
    const float* pts  = (const float*)d_in[0];   // [B,N,3] f32
    const float* feat = (const float*)d_in[1];   // [B,N,C] f32
    float* out = (float*)d_out;                  // [B,H,W,C] f32
    int n = in_sizes[0] / 3;                     // B=1 -> N
    if (n > MAXN) n = MAXN;

    render_kernel<<<NTILES, TPB>>>(pts, feat, out, n);
}

// round 5
// speedup vs baseline: 1.2429x; 1.0304x over previous
#include <cuda_runtime.h>

// Problem constants (fixed by dataset): B=1, N=4096, C=8, H=W=128, K=8
#define MAXN 8192
constexpr float RADIUS = 0.05f;
constexpr int H = 128, W = 128, C = 8, K = 8;
constexpr int TILE = 8;             // 8x8 pixel tiles
constexpr int TX = W / TILE;        // 16
constexpr int TY = H / TILE;        // 16
constexpr int NTILES = TX * TY;     // 256 blocks, one per tile
constexpr int PIX = TILE * TILE;    // 64 pixels per tile
constexpr int SPLIT = 4;            // threads per pixel in scan phase
constexpr int TPB = PIX * SPLIT;    // 256 threads per block
constexpr int CAPT = 1280;          // smem candidate cap (expected ~52, huge margin)
constexpr int LISTN = PIX * SPLIT * K;   // 2048 merge-list entries

__global__ void __launch_bounds__(TPB)
render_kernel(const float* __restrict__ pts,
              const float* __restrict__ feat,
              float* __restrict__ out, int n) {
    __shared__ __align__(16) unsigned char raw[CAPT * 16 + LISTN * 12];
    float4* s_cand = (float4*)raw;
    float*  s_mz   = (float*)(raw + CAPT * 16);
    float*  s_md   = (float*)(raw + CAPT * 16 + LISTN * 4);
    int*    s_mi   = (int*)  (raw + CAPT * 16 + LISTN * 8);
    __shared__ int s_cnt;

    const int tile = blockIdx.x;
    const int tx = tile & (TX - 1);
    const int ty = tile >> 4;

    if (threadIdx.x == 0) s_cnt = 0;
    __syncthreads();

    // Tile bounds over pixel centers, expanded by splat radius + fp-safety pad.
    // (Conservative bbox; the exact d2 < r2 test in the scan keeps correctness.)
    const float EPS = 1e-5f;
    const float x0 = ((float)(tx * TILE)            + 0.5f) * (2.0f / W) - 1.0f - RADIUS - EPS;
    const float x1 = ((float)(tx * TILE + TILE - 1) + 0.5f) * (2.0f / W) - 1.0f + RADIUS + EPS;
    const float y0 = ((float)(ty * TILE)            + 0.5f) * (2.0f / H) - 1.0f - RADIUS - EPS;
    const float y1 = ((float)(ty * TILE + TILE - 1) + 0.5f) * (2.0f / H) - 1.0f + RADIUS + EPS;

    // -------- Phase 1: division-free cull. For z>0: x/z >= x0  <=>  x >= x0*z.
    // Exact IEEE division only for the rare survivors (~52 per block).
    #pragma unroll 4
    for (int i = threadIdx.x; i < n; i += TPB) {
        float x = pts[3 * i + 0];
        float y = pts[3 * i + 1];
        float z = pts[3 * i + 2];
        bool hit = (z > 0.0f) &&
                   (x >= x0 * z) && (x <= x1 * z) &&
                   (y >= y0 * z) && (y <= y1 * z);
        if (hit) {
            float px = x / z;           // exact, matches reference projection
            float py = y / z;
            int slot = atomicAdd(&s_cnt, 1);
            if (slot < CAPT)
                s_cand[slot] = make_float4(px, py, z, __int_as_float(i));
        }
    }
    __syncthreads();
    const int cnt = min(s_cnt, CAPT);

    // -------- Phase 2: split scan, 4 threads per pixel
    const int p = threadIdx.x >> 2;        // pixel 0..63
    const int s = threadIdx.x & 3;         // sub-lane 0..3
    const int lx = p & (TILE - 1);
    const int ly = p >> 3;
    const int ix = tx * TILE + lx;
    const int iy = ty * TILE + ly;

    const float gx = ((float)ix + 0.5f) * (2.0f / W) - 1.0f;
    const float gy = ((float)iy + 0.5f) * (2.0f / H) - 1.0f;
    const float r2 = RADIUS * RADIUS;

    float lz[K], ld[K];
    int   li[K];
    #pragma unroll
    for (int k = 0; k < K; k++) { lz[k] = 3.0e38f; ld[k] = 0.0f; li[k] = 0; }

    for (int j = s; j < cnt; j += SPLIT) {
        float4 c = s_cand[j];
        float dx = gx - c.x;
        float dy = gy - c.y;
        float d2 = dx * dx + dy * dy;
        // distinct depths -> top-K set is order-independent (matches top_k)
        if (d2 < r2 && c.z < lz[K - 1]) {
            lz[K - 1] = c.z; ld[K - 1] = d2; li[K - 1] = __float_as_int(c.w);
            #pragma unroll
            for (int k = K - 1; k > 0; k--) {
                if (lz[k] < lz[k - 1]) {
                    float t0 = lz[k]; lz[k] = lz[k - 1]; lz[k - 1] = t0;
                    float t1 = ld[k]; ld[k] = ld[k - 1]; ld[k - 1] = t1;
                    int   t2 = li[k]; li[k] = li[k - 1]; li[k - 1] = t2;
                }
            }
        }
    }

    // publish local sorted top-8 lists
    {
        int off = (p * SPLIT + s) * K;
        #pragma unroll
        for (int k = 0; k < K; k++) {
            s_mz[off + k] = lz[k];
            s_md[off + k] = ld[k];
            s_mi[off + k] = li[k];
        }
    }
    __syncthreads();

    // -------- Phase 3: 4-way merge + composite + store (one thread per pixel)
    if (s == 0) {
        int   hp[SPLIT];
        float hz[SPLIT];
        #pragma unroll
        for (int q = 0; q < SPLIT; q++) {
            hp[q] = (p * SPLIT + q) * K;
            hz[q] = s_mz[hp[q]];
        }

        float acc[C];
        #pragma unroll
        for (int c = 0; c < C; c++) acc[c] = 0.0f;
        float T = 1.0f;
        const float inv_r2 = 1.0f / r2;

        #pragma unroll
        for (int k = 0; k < K; k++) {
            int b = 0;
            if (hz[1] < hz[b]) b = 1;
            if (hz[2] < hz[b]) b = 2;
            if (hz[3] < hz[b]) b = 3;
            float zk = hz[b];
            if (zk < 1.0e38f) {
                float d2 = s_md[hp[b]];
                int   id = s_mi[hp[b]];
                float a = 1.0f - d2 * inv_r2;
                a = fminf(fmaxf(a, 0.0f), 1.0f);
                float w = a * T;
                const float4* f = (const float4*)(feat + (size_t)id * C);
                float4 f0 = __ldg(&f[0]);
                float4 f1 = __ldg(&f[1]);
                acc[0] += w * f0.x; acc[1] += w * f0.y;
                acc[2] += w * f0.z; acc[3] += w * f0.w;
                acc[4] += w * f1.x; acc[5] += w * f1.y;
                acc[6] += w * f1.z; acc[7] += w * f1.w;
                T *= (1.0f - a);
            }
            hp[b]++;
            hz[b] = ((hp[b] & (K - 1)) != 0) ? s_mz[hp[b]] : 3.0e38f;
        }

        float4* o = (float4*)(out + (size_t)(iy * W + ix) * C);
        o[0] = make_float4(acc[0], acc[1], acc[2], acc[3]);
        o[1] = make_float4(acc[4], acc[5], acc[6], acc[7]);
    }
}

extern "C" void kernel_launch(void* const* d_in, const int* in_sizes, int n_in,
                              void* d_out, int out_size) {
    const float* pts  = (const float*)d_in[0];   // [B,N,3] f32
    const float* feat = (const float*)d_in[1];   // [B,N,C] f32
    float* out = (float*)d_out;                  // [B,H,W,C] f32
    int n = in_sizes[0] / 3;                     // B=1 -> N
    if (n > MAXN) n = MAXN;

    render_kernel<<<NTILES, TPB>>>(pts, feat, out, n);
}